// round 1
// baseline (speedup 1.0000x reference)
#include <cuda_runtime.h>
#include <cstdint>

#define H     128
#define NENT  40000
#define NREL  256
#define NJ    129     // 129 att-intervals (128 breakpoints)
#define TILE_E 16
#define KC     32

// ---------------- scratch (device globals; no allocation) ----------------
__device__ float2 g_Ps[NENT * H];   // {P3s, P4s} per (entity, h)   ~41MB
__device__ float2 g_Pr[NREL * H];   // {P3r, P4r + W4_b}
__device__ float2 g_AC[NJ * H];     // {A_j, C_j} piecewise table (W3_b folded into C)
__device__ float  g_thr[H];         // sorted breakpoints
__device__ int    g_rank[H];        // rank of breakpoint k in sorted order
__device__ float2 g_wqs[H * H];     // [k][h] = {W3s^T, W4s^T}
__device__ float2 g_wqr[H * H];     // [k][h] = {W3r^T, W4r^T}

// ---------------- K0a: breakpoints + ranks (1 block) ----------------
__global__ void k0a_thresholds(const float* __restrict__ w1,
                               const float* __restrict__ b1) {
    __shared__ float tsh[H];
    int k = threadIdx.x;
    float w = w1[k], b = b1[k];
    float t = (w != 0.0f) ? (-b / w) : __int_as_float(0x7f800000); // +inf if w1==0
    tsh[k] = t;
    __syncthreads();
    int r = 0;
    #pragma unroll 8
    for (int j = 0; j < H; ++j) {
        float tj = tsh[j];
        r += (tj < t) || (tj == t && j < k);
    }
    g_thr[r] = t;
    g_rank[k] = r;
}

// ---------------- K0b: build (A_j, C_j) table (129 blocks) ----------------
// Active set in interval j (att above the j smallest breakpoints):
//   w1>0 : active iff rank < j
//   w1<0 : active iff rank >= j
//   w1==0: active iff b1 > 0 (constant; contributes only to C)
__global__ void k0b_actable(const float* __restrict__ w1,
                            const float* __restrict__ b1,
                            const float* __restrict__ W3,
                            const float* __restrict__ W3b) {
    __shared__ float w1s[H], b1s[H];
    __shared__ int rks[H];
    int h = threadIdx.x, j = blockIdx.x;
    w1s[h] = w1[h]; b1s[h] = b1[h]; rks[h] = g_rank[h];
    __syncthreads();
    float a = 0.0f, c = W3b[h];
    const float* row = W3 + h * 384;   // W3a = cols [0,128)
    for (int k = 0; k < H; ++k) {
        float w = w1s[k], b = b1s[k];
        bool act = (w > 0.0f) ? (rks[k] < j)
                 : (w < 0.0f) ? (rks[k] >= j)
                              : (b > 0.0f);
        if (act) {
            float m = row[k];
            a = fmaf(m, w, a);
            c = fmaf(m, b, c);
        }
    }
    g_AC[j * H + h] = make_float2(a, c);
}

// ---------------- K0c: transpose/pack weights (128 blocks) ----------------
__global__ void k0c_packw(const float* __restrict__ W3,
                          const float* __restrict__ W4) {
    int k = blockIdx.x, h = threadIdx.x;
    g_wqs[k * H + h] = make_float2(W3[h * 384 + 128 + k], W4[h * 256 + k]);
    g_wqr[k * H + h] = make_float2(W3[h * 384 + 256 + k], W4[h * 256 + 128 + k]);
}

// ---------------- K1: projection "GEMM" (entities or relations) ----------------
// out[n][h] = { embeds[n] . wq[.][h].x , embeds[n] . wq[.][h].y (+ b4[h]) }
__global__ void kproj(const float* __restrict__ embeds,
                      const float2* __restrict__ wq,
                      float2* __restrict__ out,
                      const float* __restrict__ b4) {  // may be null
    __shared__ float2 wq_sm[KC * H];        // 32 KB
    __shared__ float  emb_sm[TILE_E * H];   // 8 KB
    int tid = threadIdx.x;
    int e0 = blockIdx.x * TILE_E;

    // stage TILE_E embeddings (coalesced float4)
    const float4* src = (const float4*)(embeds + (size_t)e0 * H);
    float4* dst = (float4*)emb_sm;
    #pragma unroll
    for (int i = 0; i < (TILE_E * H / 4) / H; ++i)
        dst[tid + i * H] = src[tid + i * H];

    float acc3[TILE_E], acc4[TILE_E];
    #pragma unroll
    for (int e = 0; e < TILE_E; ++e) { acc3[e] = 0.0f; acc4[e] = 0.0f; }

    for (int kc = 0; kc < H / KC; ++kc) {
        __syncthreads();
        #pragma unroll
        for (int i = 0; i < KC; ++i)
            wq_sm[tid + i * H] = wq[(size_t)kc * KC * H + tid + i * H];
        __syncthreads();
        #pragma unroll
        for (int k4 = 0; k4 < KC / 4; ++k4) {
            float2 w0 = wq_sm[(k4 * 4 + 0) * H + tid];
            float2 w1 = wq_sm[(k4 * 4 + 1) * H + tid];
            float2 w2 = wq_sm[(k4 * 4 + 2) * H + tid];
            float2 w3 = wq_sm[(k4 * 4 + 3) * H + tid];
            #pragma unroll
            for (int e = 0; e < TILE_E; ++e) {
                float4 v = *(const float4*)&emb_sm[e * H + kc * KC + k4 * 4];
                acc3[e] = fmaf(v.x, w0.x, acc3[e]); acc4[e] = fmaf(v.x, w0.y, acc4[e]);
                acc3[e] = fmaf(v.y, w1.x, acc3[e]); acc4[e] = fmaf(v.y, w1.y, acc4[e]);
                acc3[e] = fmaf(v.z, w2.x, acc3[e]); acc4[e] = fmaf(v.z, w2.y, acc4[e]);
                acc3[e] = fmaf(v.w, w3.x, acc3[e]); acc4[e] = fmaf(v.w, w3.y, acc4[e]);
            }
        }
    }
    float bb = (b4 != nullptr) ? b4[tid] : 0.0f;
    #pragma unroll
    for (int e = 0; e < TILE_E; ++e)
        out[(size_t)(e0 + e) * H + tid] = make_float2(acc3[e], acc4[e] + bb);
}

// ---------------- K2: per-segment aggregation + fused output assembly ----------------
// block t = (b, l). One thread per h.
__global__ void kedge(const int* __restrict__ seg,
                      const int* __restrict__ nent,
                      const int* __restrict__ nrel,
                      const float* __restrict__ natt,
                      const float* __restrict__ self_att,
                      const int* __restrict__ s_ids,
                      const int* __restrict__ r_ids,
                      const float* __restrict__ ent_embeds,
                      const float* __restrict__ rel_embeds,
                      const float* __restrict__ w1,
                      const float* __restrict__ b1,
                      float* __restrict__ out,
                      int E, int L, int T) {
    __shared__ float thr_sm[H];
    __shared__ int bnd[2];
    int tid = threadIdx.x;
    int t = blockIdx.x;
    thr_sm[tid] = g_thr[tid];
    if (tid < 2) {
        int target = t + tid;
        int lo = 0, hi = E;
        while (lo < hi) {
            int m = (lo + hi) >> 1;
            if (seg[m] < target) lo = m + 1; else hi = m;
        }
        bnd[tid] = lo;
    }
    __syncthreads();
    int lo = bnd[0], hi = bnd[1];

    float acc_e = 0.0f, acc_s = 0.0f;
    #pragma unroll 2
    for (int i = lo; i < hi; ++i) {
        int   ent = __ldg(&nent[i]);
        int   rel = __ldg(&nrel[i]);
        float att = __ldg(&natt[i]);
        // branchless lower_bound: pos = #(thr < att)
        int pos = 0;
        #pragma unroll
        for (int w = 64; w >= 1; w >>= 1)
            if (thr_sm[pos + w - 1] < att) pos += w;
        float2 ps = g_Ps[(size_t)ent * H + tid];
        float2 pr = g_Pr[(size_t)rel * H + tid];
        float2 ac = g_AC[(size_t)pos * H + tid];
        acc_e += fmaxf(fmaf(att, ac.x, ac.y) + ps.x + pr.x, 0.0f);
        acc_s += fmaxf(ps.y + pr.y, 0.0f);
    }
    float denom = fmaxf((float)(hi - lo), 1.0f);
    float me = acc_e / denom;
    float ms = acc_s / denom;

    int b = t / L;
    float es = ent_embeds[(size_t)__ldg(&s_ids[b]) * H + tid];
    float er = rel_embeds[(size_t)__ldg(&r_ids[b]) * H + tid];
    float sa = __ldg(&self_att[t]);
    float sae = fmaxf(fmaf(sa, w1[tid], b1[tid]), 0.0f);

    float* out1 = out + (size_t)t * 3 * H;                      // s_embed_seq
    float* out2 = out + (size_t)T * 3 * H + (size_t)t * 3 * H;  // att_embed_seq
    out1[tid]         = es;
    out1[H + tid]     = er;
    out1[2 * H + tid] = ms;
    out2[tid]         = sae;
    out2[H + tid]     = es;
    out2[2 * H + tid] = me;
}

// ---------------- launch ----------------
extern "C" void kernel_launch(void* const* d_in, const int* in_sizes, int n_in,
                              void* d_out, int out_size) {
    const int*   nbr_ent  = (const int*)  d_in[0];
    const int*   nbr_rel  = (const int*)  d_in[1];
    const float* nbr_att  = (const float*)d_in[2];
    const int*   seg_ids  = (const int*)  d_in[3];
    const float* self_att = (const float*)d_in[4];
    const int*   s_ids    = (const int*)  d_in[5];
    const int*   r_ids    = (const int*)  d_in[6];
    const float* ent_emb  = (const float*)d_in[7];
    const float* rel_emb  = (const float*)d_in[8];
    const float* W1w      = (const float*)d_in[9];
    const float* W1b      = (const float*)d_in[10];
    const float* W3w      = (const float*)d_in[11];
    const float* W3b      = (const float*)d_in[12];
    const float* W4w      = (const float*)d_in[13];
    const float* W4b      = (const float*)d_in[14];

    int E = in_sizes[0];
    int B = in_sizes[5];
    int L = in_sizes[4] / B;
    int T = B * L;
    int nent = in_sizes[7] / H;   // 40000
    int nrel = in_sizes[8] / H;   // 256

    void *pPs, *pPr, *pWqs, *pWqr;
    cudaGetSymbolAddress(&pPs, g_Ps);
    cudaGetSymbolAddress(&pPr, g_Pr);
    cudaGetSymbolAddress(&pWqs, g_wqs);
    cudaGetSymbolAddress(&pWqr, g_wqr);

    k0a_thresholds<<<1, H>>>(W1w, W1b);
    k0b_actable<<<NJ, H>>>(W1w, W1b, W3w, W3b);
    k0c_packw<<<H, H>>>(W3w, W4w);

    kproj<<<nent / TILE_E, H>>>(ent_emb, (const float2*)pWqs, (float2*)pPs, nullptr);
    kproj<<<nrel / TILE_E, H>>>(rel_emb, (const float2*)pWqr, (float2*)pPr, W4b);

    kedge<<<T, H>>>(seg_ids, nbr_ent, nbr_rel, nbr_att, self_att,
                    s_ids, r_ids, ent_emb, rel_emb, W1w, W1b,
                    (float*)d_out, E, L, T);
}

// round 3
// speedup vs baseline: 1.0545x; 1.0545x over previous
#include <cuda_runtime.h>
#include <cuda_fp16.h>
#include <cstdint>

#define H     128
#define NENT  40000
#define NREL  256
#define NJ    129     // 129 att-intervals (128 breakpoints)
#define TE    8       // entities per tile in kproj2

// ---------------- scratch (device globals; no allocation) ----------------
__device__ __half2 g_Ps[NENT * H];  // {P3s, P4s} per (entity, h)  ~20.5MB
__device__ __half2 g_Pr[NREL * H];  // {P3r, P4r + W4_b}           128KB (L1-resident)
__device__ __half2 g_AC[NJ * H];    // {A_j, C_j} piecewise table   66KB (L1-resident)
__device__ float   g_thr[H];        // sorted breakpoints
__device__ int     g_rank[H];       // rank of breakpoint k in sorted order
__device__ float2  g_wqs[H * H];    // [k][h] = {W3s^T, W4s^T}  (fp32 for accuracy)
__device__ float2  g_wqr[H * H];    // [k][h] = {W3r^T, W4r^T}

// ---------------- K0a: breakpoints + ranks (1 block) ----------------
__global__ void k0a_thresholds(const float* __restrict__ w1,
                               const float* __restrict__ b1) {
    __shared__ float tsh[H];
    int k = threadIdx.x;
    float w = w1[k], b = b1[k];
    float t = (w != 0.0f) ? (-b / w) : __int_as_float(0x7f800000); // +inf if w1==0
    tsh[k] = t;
    __syncthreads();
    int r = 0;
    #pragma unroll 8
    for (int j = 0; j < H; ++j) {
        float tj = tsh[j];
        r += (tj < t) || (tj == t && j < k);
    }
    g_thr[r] = t;
    g_rank[k] = r;
}

// ---------------- K0b: build (A_j, C_j) table (129 blocks) ----------------
__global__ void k0b_actable(const float* __restrict__ w1,
                            const float* __restrict__ b1,
                            const float* __restrict__ W3,
                            const float* __restrict__ W3b) {
    __shared__ float w1s[H], b1s[H];
    __shared__ int rks[H];
    int h = threadIdx.x, j = blockIdx.x;
    w1s[h] = w1[h]; b1s[h] = b1[h]; rks[h] = g_rank[h];
    __syncthreads();
    float a = 0.0f, c = W3b[h];
    const float* row = W3 + h * 384;   // W3a = cols [0,128)
    for (int k = 0; k < H; ++k) {
        float w = w1s[k], b = b1s[k];
        bool act = (w > 0.0f) ? (rks[k] < j)
                 : (w < 0.0f) ? (rks[k] >= j)
                              : (b > 0.0f);
        if (act) {
            float m = row[k];
            a = fmaf(m, w, a);
            c = fmaf(m, b, c);
        }
    }
    g_AC[j * H + h] = __floats2half2_rn(a, c);
}

// ---------------- K0c: transpose/pack weights (128 blocks) ----------------
__global__ void k0c_packw(const float* __restrict__ W3,
                          const float* __restrict__ W4) {
    int k = blockIdx.x, h = threadIdx.x;
    g_wqs[k * H + h] = make_float2(W3[h * 384 + 128 + k], W4[h * 256 + k]);
    g_wqr[k * H + h] = make_float2(W3[h * 384 + 256 + k], W4[h * 256 + 128 + k]);
}

// ---------------- K1: projection, k-split, weights in registers ----------------
// 512 threads: h = tid&127, ks = tid>>7 (k-slice of 32).
// Each thread: 32 float2 weights in registers. Persistent over entity tiles.
__global__ void __launch_bounds__(512, 1)
kproj2(const float* __restrict__ embeds,
       const float2* __restrict__ wq,
       __half2* __restrict__ out,
       const float* __restrict__ b4,   // may be null
       int n) {
    __shared__ float  emb_sm[TE * H];        // 4 KB
    __shared__ float2 red[3 * TE * H];       // 24 KB: partials from ks=1,2,3
    int tid = threadIdx.x;
    int h = tid & 127;
    int ks = tid >> 7;

    // weights -> registers (once per block)
    float2 w[32];
    #pragma unroll
    for (int j = 0; j < 32; ++j)
        w[j] = wq[(ks * 32 + j) * H + h];
    float bb = (b4 != nullptr && ks == 0) ? b4[h] : 0.0f;

    for (int tile = blockIdx.x; tile * TE < n; tile += gridDim.x) {
        int e0 = tile * TE;
        __syncthreads();   // protect emb_sm / red reuse from previous tile
        if (tid < TE * H / 4) {
            ((float4*)emb_sm)[tid] = ((const float4*)(embeds + (size_t)e0 * H))[tid];
        }
        __syncthreads();

        float acc3[TE], acc4[TE];
        #pragma unroll
        for (int e = 0; e < TE; ++e) { acc3[e] = 0.0f; acc4[e] = 0.0f; }

        #pragma unroll
        for (int j4 = 0; j4 < 8; ++j4) {
            float2 w0 = w[j4 * 4 + 0];
            float2 w1_ = w[j4 * 4 + 1];
            float2 w2 = w[j4 * 4 + 2];
            float2 w3 = w[j4 * 4 + 3];
            #pragma unroll
            for (int e = 0; e < TE; ++e) {
                float4 v = *(const float4*)&emb_sm[e * H + ks * 32 + j4 * 4];
                acc3[e] = fmaf(v.x, w0.x, acc3[e]);  acc4[e] = fmaf(v.x, w0.y, acc4[e]);
                acc3[e] = fmaf(v.y, w1_.x, acc3[e]); acc4[e] = fmaf(v.y, w1_.y, acc4[e]);
                acc3[e] = fmaf(v.z, w2.x, acc3[e]);  acc4[e] = fmaf(v.z, w2.y, acc4[e]);
                acc3[e] = fmaf(v.w, w3.x, acc3[e]);  acc4[e] = fmaf(v.w, w3.y, acc4[e]);
            }
        }

        // reduction across ks groups: ks 1..3 write, ks 0 reads+stores
        if (ks >= 1) {
            float2* dst = red + (ks - 1) * TE * H;
            #pragma unroll
            for (int e = 0; e < TE; ++e)
                dst[e * H + h] = make_float2(acc3[e], acc4[e]);
        }
        __syncthreads();
        if (ks == 0) {
            #pragma unroll
            for (int e = 0; e < TE; ++e) {
                float2 p0 = red[0 * TE * H + e * H + h];
                float2 p1 = red[1 * TE * H + e * H + h];
                float2 p2 = red[2 * TE * H + e * H + h];
                float s3 = acc3[e] + p0.x + p1.x + p2.x;
                float s4 = acc4[e] + p0.y + p1.y + p2.y + bb;
                if (e0 + e < n)
                    out[(size_t)(e0 + e) * H + h] = __floats2half2_rn(s3, s4);
            }
        }
    }
}

// ---------------- K2: per-segment aggregation + fused output assembly ----------------
__global__ void kedge(const int* __restrict__ seg,
                      const int* __restrict__ nent,
                      const int* __restrict__ nrel,
                      const float* __restrict__ natt,
                      const float* __restrict__ self_att,
                      const int* __restrict__ s_ids,
                      const int* __restrict__ r_ids,
                      const float* __restrict__ ent_embeds,
                      const float* __restrict__ rel_embeds,
                      const float* __restrict__ w1,
                      const float* __restrict__ b1,
                      float* __restrict__ out,
                      int E, int L, int T) {
    __shared__ float thr_sm[H];
    __shared__ int bnd[2];
    int tid = threadIdx.x;
    int t = blockIdx.x;
    thr_sm[tid] = g_thr[tid];
    if (tid < 2) {
        int target = t + tid;
        int lo = 0, hi = E;
        while (lo < hi) {
            int m = (lo + hi) >> 1;
            if (seg[m] < target) lo = m + 1; else hi = m;
        }
        bnd[tid] = lo;
    }
    __syncthreads();
    int lo = bnd[0], hi = bnd[1];

    float acc_e = 0.0f, acc_s = 0.0f;
    #pragma unroll 4
    for (int i = lo; i < hi; ++i) {
        int   ent = __ldg(&nent[i]);
        int   rel = __ldg(&nrel[i]);
        float att = __ldg(&natt[i]);
        // branchless lower_bound: pos = #(thr < att)
        int pos = 0;
        #pragma unroll
        for (int w = 64; w >= 1; w >>= 1)
            if (thr_sm[pos + w - 1] < att) pos += w;
        float2 ps = __half22float2(g_Ps[(size_t)ent * H + tid]);
        float2 pr = __half22float2(g_Pr[(size_t)rel * H + tid]);
        float2 ac = __half22float2(g_AC[(size_t)pos * H + tid]);
        acc_e += fmaxf(fmaf(att, ac.x, ac.y) + ps.x + pr.x, 0.0f);
        acc_s += fmaxf(ps.y + pr.y, 0.0f);
    }
    float denom = fmaxf((float)(hi - lo), 1.0f);
    float me = acc_e / denom;
    float ms = acc_s / denom;

    int b = t / L;
    float es = ent_embeds[(size_t)__ldg(&s_ids[b]) * H + tid];
    float er = rel_embeds[(size_t)__ldg(&r_ids[b]) * H + tid];
    float sa = __ldg(&self_att[t]);
    float sae = fmaxf(fmaf(sa, w1[tid], b1[tid]), 0.0f);

    float* out1 = out + (size_t)t * 3 * H;                      // s_embed_seq
    float* out2 = out + (size_t)T * 3 * H + (size_t)t * 3 * H;  // att_embed_seq
    out1[tid]         = es;
    out1[H + tid]     = er;
    out1[2 * H + tid] = ms;
    out2[tid]         = sae;
    out2[H + tid]     = es;
    out2[2 * H + tid] = me;
}

// ---------------- launch ----------------
extern "C" void kernel_launch(void* const* d_in, const int* in_sizes, int n_in,
                              void* d_out, int out_size) {
    const int*   nbr_ent  = (const int*)  d_in[0];
    const int*   nbr_rel  = (const int*)  d_in[1];
    const float* nbr_att  = (const float*)d_in[2];
    const int*   seg_ids  = (const int*)  d_in[3];
    const float* self_att = (const float*)d_in[4];
    const int*   s_ids    = (const int*)  d_in[5];
    const int*   r_ids    = (const int*)  d_in[6];
    const float* ent_emb  = (const float*)d_in[7];
    const float* rel_emb  = (const float*)d_in[8];
    const float* W1w      = (const float*)d_in[9];
    const float* W1b      = (const float*)d_in[10];
    const float* W3w      = (const float*)d_in[11];
    const float* W3b      = (const float*)d_in[12];
    const float* W4w      = (const float*)d_in[13];
    const float* W4b      = (const float*)d_in[14];

    int E = in_sizes[0];
    int B = in_sizes[5];
    int L = in_sizes[4] / B;
    int T = B * L;
    int nent = in_sizes[7] / H;   // 40000
    int nrel = in_sizes[8] / H;   // 256

    void *pPs, *pPr, *pWqs, *pWqr;
    cudaGetSymbolAddress(&pPs, g_Ps);
    cudaGetSymbolAddress(&pPr, g_Pr);
    cudaGetSymbolAddress(&pWqs, g_wqs);
    cudaGetSymbolAddress(&pWqr, g_wqr);

    k0a_thresholds<<<1, H>>>(W1w, W1b);
    k0b_actable<<<NJ, H>>>(W1w, W1b, W3w, W3b);
    k0c_packw<<<H, H>>>(W3w, W4w);

    kproj2<<<148, 512>>>(ent_emb, (const float2*)pWqs, (__half2*)pPs, nullptr, nent);
    kproj2<<<32, 512>>>(rel_emb, (const float2*)pWqr, (__half2*)pPr, W4b, nrel);

    kedge<<<T, H>>>(seg_ids, nbr_ent, nbr_rel, nbr_att, self_att,
                    s_ids, r_ids, ent_emb, rel_emb, W1w, W1b,
                    (float*)d_out, E, L, T);
}

// round 4
// speedup vs baseline: 1.1880x; 1.1266x over previous
#include <cuda_runtime.h>
#include <cuda_fp16.h>
#include <cstdint>

#define H     128
#define NENT  40000
#define NREL  256
#define NJ    129     // 129 att-intervals (128 breakpoints)
#define TE    8       // entities per tile in kproj2
#define TMAX  10241

typedef unsigned long long ull;

// ---------------- scratch (device globals; no allocation) ----------------
__device__ __half2 g_Ps[NENT * H];  // {P3s, P4s} per (entity, h)  ~20.5MB
__device__ __half2 g_Pr[NREL * H];  // {P3r, P4r + W4_b}           128KB
__device__ __half2 g_AC[NJ * H];    // {A_j, C_j} piecewise table   66KB
__device__ float   g_thr[H];        // sorted breakpoints
__device__ int     g_rank[H];       // rank of breakpoint k
__device__ float2  g_wqs[H * H];    // [k][h] = {W3s^T, W4s^T}
__device__ float2  g_wqr[H * H];    // [k][h] = {W3r^T, W4r^T}
__device__ int     g_off[TMAX];     // segment start offsets

__device__ __forceinline__ void fma2(ull& acc, ull a, ull b) {
    asm("fma.rn.f32x2 %0, %1, %2, %0;" : "+l"(acc) : "l"(a), "l"(b));
}

// ---------------- K0a: breakpoints + ranks (1 block) ----------------
__global__ void k0a_thresholds(const float* __restrict__ w1,
                               const float* __restrict__ b1) {
    __shared__ float tsh[H];
    int k = threadIdx.x;
    float w = w1[k], b = b1[k];
    float t = (w != 0.0f) ? (-b / w) : __int_as_float(0x7f800000);
    tsh[k] = t;
    __syncthreads();
    int r = 0;
    #pragma unroll 8
    for (int j = 0; j < H; ++j) {
        float tj = tsh[j];
        r += (tj < t) || (tj == t && j < k);
    }
    g_thr[r] = t;
    g_rank[k] = r;
}

// ---------------- K0b: build (A_j, C_j) table (129 blocks) ----------------
__global__ void k0b_actable(const float* __restrict__ w1,
                            const float* __restrict__ b1,
                            const float* __restrict__ W3,
                            const float* __restrict__ W3b) {
    __shared__ float w1s[H], b1s[H];
    __shared__ int rks[H];
    int h = threadIdx.x, j = blockIdx.x;
    w1s[h] = w1[h]; b1s[h] = b1[h]; rks[h] = g_rank[h];
    __syncthreads();
    float a = 0.0f, c = W3b[h];
    const float* row = W3 + h * 384;   // W3a = cols [0,128)
    for (int k = 0; k < H; ++k) {
        float w = w1s[k], b = b1s[k];
        bool act = (w > 0.0f) ? (rks[k] < j)
                 : (w < 0.0f) ? (rks[k] >= j)
                              : (b > 0.0f);
        if (act) {
            float m = row[k];
            a = fmaf(m, w, a);
            c = fmaf(m, b, c);
        }
    }
    g_AC[j * H + h] = __floats2half2_rn(a, c);
}

// ---------------- K0c: transpose/pack weights (128 blocks) ----------------
__global__ void k0c_packw(const float* __restrict__ W3,
                          const float* __restrict__ W4) {
    int k = blockIdx.x, h = threadIdx.x;
    g_wqs[k * H + h] = make_float2(W3[h * 384 + 128 + k], W4[h * 256 + k]);
    g_wqr[k * H + h] = make_float2(W3[h * 384 + 256 + k], W4[h * 256 + 128 + k]);
}

// ---------------- K0d: segment start offsets (parallel binary searches) --------
__global__ void kbounds(const int* __restrict__ seg, int E, int T) {
    int t = blockIdx.x * blockDim.x + threadIdx.x;
    if (t > T) return;
    int lo = 0, hi = E;
    while (lo < hi) {
        int m = (lo + hi) >> 1;
        if (seg[m] < t) lo = m + 1; else hi = m;
    }
    g_off[t] = lo;
}

// ---------------- K1: projection, k-split, FFMA2, weights in registers --------
// 512 threads: h = tid&127, ks = tid>>7 (k-slice of 32).
__global__ void __launch_bounds__(512, 1)
kproj2(const float* __restrict__ embeds,
       const ull* __restrict__ wq,     // float2 pairs as b64
       __half2* __restrict__ out,
       const float* __restrict__ b4,   // may be null
       int n) {
    __shared__ float2 emb2_sm[TE * H];       // 8 KB: duplicated {v,v}
    __shared__ float2 red[3 * TE * H];       // 24 KB: partials from ks=1,2,3
    int tid = threadIdx.x;
    int h = tid & 127;
    int ks = tid >> 7;

    // weights -> registers (once per block), packed b64 {w3,w4}
    ull w[32];
    #pragma unroll
    for (int j = 0; j < 32; ++j)
        w[j] = wq[(ks * 32 + j) * H + h];
    float bb = (b4 != nullptr && ks == 0) ? b4[h] : 0.0f;

    for (int tile = blockIdx.x; tile * TE < n; tile += gridDim.x) {
        int e0 = tile * TE;
        __syncthreads();   // protect emb2_sm / red reuse
        {
            float a = embeds[(size_t)e0 * H + tid];
            float b = embeds[(size_t)e0 * H + tid + 512];
            emb2_sm[tid]       = make_float2(a, a);
            emb2_sm[tid + 512] = make_float2(b, b);
        }
        __syncthreads();

        ull acc[TE];
        #pragma unroll
        for (int e = 0; e < TE; ++e) acc[e] = 0ULL;

        #pragma unroll
        for (int j2 = 0; j2 < 16; ++j2) {
            #pragma unroll
            for (int e = 0; e < TE; ++e) {
                ulonglong2 vv = *(const ulonglong2*)&emb2_sm[e * H + ks * 32 + j2 * 2];
                fma2(acc[e], vv.x, w[j2 * 2 + 0]);
                fma2(acc[e], vv.y, w[j2 * 2 + 1]);
            }
        }

        // reduction across ks groups: ks 1..3 write, ks 0 reads+stores
        if (ks >= 1) {
            float2* dst = red + (ks - 1) * TE * H;
            #pragma unroll
            for (int e = 0; e < TE; ++e) {
                float2 a2;
                asm("mov.b64 {%0, %1}, %2;" : "=f"(a2.x), "=f"(a2.y) : "l"(acc[e]));
                dst[e * H + h] = a2;
            }
        }
        __syncthreads();
        if (ks == 0) {
            #pragma unroll
            for (int e = 0; e < TE; ++e) {
                float2 a2;
                asm("mov.b64 {%0, %1}, %2;" : "=f"(a2.x), "=f"(a2.y) : "l"(acc[e]));
                float2 p0 = red[0 * TE * H + e * H + h];
                float2 p1 = red[1 * TE * H + e * H + h];
                float2 p2 = red[2 * TE * H + e * H + h];
                float s3 = a2.x + p0.x + p1.x + p2.x;
                float s4 = a2.y + p0.y + p1.y + p2.y + bb;
                out[(size_t)(e0 + e) * H + h] = __floats2half2_rn(s3, s4);
            }
        }
    }
}

// ---------------- K2: per-segment aggregation + fused output assembly ---------
__global__ void kedge(const int* __restrict__ nent,
                      const int* __restrict__ nrel,
                      const float* __restrict__ natt,
                      const float* __restrict__ self_att,
                      const int* __restrict__ s_ids,
                      const int* __restrict__ r_ids,
                      const float* __restrict__ ent_embeds,
                      const float* __restrict__ rel_embeds,
                      const float* __restrict__ w1,
                      const float* __restrict__ b1,
                      float* __restrict__ out,
                      int L, int T) {
    __shared__ float thr_sm[H];
    __shared__ int   ent_s[128];
    __shared__ int   rel_s[128];
    __shared__ float att_s[128];
    __shared__ int   pos_s[128];
    int tid = threadIdx.x;
    int t = blockIdx.x;
    thr_sm[tid] = g_thr[tid];
    int lo = g_off[t];
    int hi = g_off[t + 1];
    __syncthreads();

    float acc_e = 0.0f, acc_s = 0.0f;
    for (int base = lo; base < hi; base += 128) {
        int m = min(128, hi - base);
        if (tid < m) {
            int   ent = __ldg(&nent[base + tid]);
            int   rel = __ldg(&nrel[base + tid]);
            float att = __ldg(&natt[base + tid]);
            int pos = 0;
            #pragma unroll
            for (int w = 64; w >= 1; w >>= 1)
                if (thr_sm[pos + w - 1] < att) pos += w;
            ent_s[tid] = ent; rel_s[tid] = rel; att_s[tid] = att; pos_s[tid] = pos;
        }
        __syncthreads();
        #pragma unroll 4
        for (int i = 0; i < m; ++i) {
            int   ent = ent_s[i];
            int   rel = rel_s[i];
            float att = att_s[i];
            int   pos = pos_s[i];
            float2 ps = __half22float2(g_Ps[(size_t)ent * H + tid]);
            float2 pr = __half22float2(g_Pr[(size_t)rel * H + tid]);
            float2 ac = __half22float2(g_AC[(size_t)pos * H + tid]);
            acc_e += fmaxf(fmaf(att, ac.x, ac.y) + ps.x + pr.x, 0.0f);
            acc_s += fmaxf(ps.y + pr.y, 0.0f);
        }
        __syncthreads();
    }
    float denom = fmaxf((float)(hi - lo), 1.0f);
    float me = acc_e / denom;
    float ms = acc_s / denom;

    int b = t / L;
    float es = ent_embeds[(size_t)__ldg(&s_ids[b]) * H + tid];
    float er = rel_embeds[(size_t)__ldg(&r_ids[b]) * H + tid];
    float sa = __ldg(&self_att[t]);
    float sae = fmaxf(fmaf(sa, w1[tid], b1[tid]), 0.0f);

    float* out1 = out + (size_t)t * 3 * H;                      // s_embed_seq
    float* out2 = out + (size_t)T * 3 * H + (size_t)t * 3 * H;  // att_embed_seq
    out1[tid]         = es;
    out1[H + tid]     = er;
    out1[2 * H + tid] = ms;
    out2[tid]         = sae;
    out2[H + tid]     = es;
    out2[2 * H + tid] = me;
}

// ---------------- launch ----------------
extern "C" void kernel_launch(void* const* d_in, const int* in_sizes, int n_in,
                              void* d_out, int out_size) {
    const int*   nbr_ent  = (const int*)  d_in[0];
    const int*   nbr_rel  = (const int*)  d_in[1];
    const float* nbr_att  = (const float*)d_in[2];
    const int*   seg_ids  = (const int*)  d_in[3];
    const float* self_att = (const float*)d_in[4];
    const int*   s_ids    = (const int*)  d_in[5];
    const int*   r_ids    = (const int*)  d_in[6];
    const float* ent_emb  = (const float*)d_in[7];
    const float* rel_emb  = (const float*)d_in[8];
    const float* W1w      = (const float*)d_in[9];
    const float* W1b      = (const float*)d_in[10];
    const float* W3w      = (const float*)d_in[11];
    const float* W3b      = (const float*)d_in[12];
    const float* W4w      = (const float*)d_in[13];
    const float* W4b      = (const float*)d_in[14];

    int E = in_sizes[0];
    int B = in_sizes[5];
    int L = in_sizes[4] / B;
    int T = B * L;
    int nent = in_sizes[7] / H;   // 40000
    int nrel = in_sizes[8] / H;   // 256

    void *pPs, *pPr, *pWqs, *pWqr;
    cudaGetSymbolAddress(&pPs, g_Ps);
    cudaGetSymbolAddress(&pPr, g_Pr);
    cudaGetSymbolAddress(&pWqs, g_wqs);
    cudaGetSymbolAddress(&pWqr, g_wqr);

    k0a_thresholds<<<1, H>>>(W1w, W1b);
    k0b_actable<<<NJ, H>>>(W1w, W1b, W3w, W3b);
    k0c_packw<<<H, H>>>(W3w, W4w);
    kbounds<<<(T + 256) / 256, 256>>>(seg_ids, E, T);

    kproj2<<<148, 512>>>(ent_emb, (const ull*)pWqs, (__half2*)pPs, nullptr, nent);
    kproj2<<<32, 512>>>(rel_emb, (const ull*)pWqr, (__half2*)pPr, W4b, nrel);

    kedge<<<T, H>>>(nbr_ent, nbr_rel, nbr_att, self_att,
                    s_ids, r_ids, ent_emb, rel_emb, W1w, W1b,
                    (float*)d_out, L, T);
}